// round 16
// baseline (speedup 1.0000x reference)
#include <cuda_runtime.h>
#include <cuda_fp16.h>
#include <math.h>
#include <stdint.h>

#define D      256
#define NTOK   32768
#define ND     (NTOK * D)
#define DD     (D * D)
#define LRc    1e-3f
#define WDc    1e-2f
#define EPSc   1e-8f

// ---------------- scratch (device globals: allocation-free) ----------------
__device__ __half g_xbh[ND];
__device__ __half g_keysh[ND], g_keysl[ND];
__device__ __half g_qh[ND],   g_ql[ND];
__device__ __half g_h1h[ND],  g_h1l[ND];
__device__ __half g_dz2h[ND];
__device__ __half g_dz1h[ND];
__device__ __half g_h1qh[ND], g_h1ql[ND];
__device__ __half g_g1[ND], g_dp[ND];          // fp16 intermediates
__device__ __half g_valh[ND];                  // values target, fp16
__device__ __half g_wbh[6 * DD];
__device__ __half g_nwth[2 * DD];
__device__ float g_part[128 * DD];
__device__ float g_gbp[2 * 256 * 256];
__device__ float g_nb[2 * D], g_alr[NTOK];

// fast sigmoid: MUFU.EX2 + MUFU.RCP path (~4 instrs)
__device__ __forceinline__ float sigm(float z) {
    return __fdividef(1.0f, 1.0f + __expf(-z));
}

__device__ __forceinline__ uint32_t pack2h(float a, float b) {
    return (uint32_t)__half_as_ushort(__float2half_rn(a))
         | ((uint32_t)__half_as_ushort(__float2half_rn(b)) << 16);
}

__device__ __forceinline__ uint32_t smem_u32(const void* p) {
    uint32_t a;
    asm("{ .reg .u64 t; cvta.to.shared.u64 t, %1; cvt.u32.u64 %0, t; }"
        : "=r"(a) : "l"(p));
    return a;
}

__device__ __forceinline__ void cp16(uint32_t dst, const void* src) {
    asm volatile("cp.async.cg.shared.global [%0], [%1], 16;"
                 :: "r"(dst), "l"(src) : "memory");
}
__device__ __forceinline__ void cp_commit() {
    asm volatile("cp.async.commit_group;" ::: "memory");
}
template <int N>
__device__ __forceinline__ void cp_wait() {
    asm volatile("cp.async.wait_group %0;" :: "n"(N) : "memory");
}

__device__ __forceinline__ void ldsm4(uint32_t* r, uint32_t a) {
    asm volatile("ldmatrix.sync.aligned.m8n8.x4.shared.b16 {%0,%1,%2,%3}, [%4];"
                 : "=r"(r[0]), "=r"(r[1]), "=r"(r[2]), "=r"(r[3]) : "r"(a));
}
__device__ __forceinline__ void ldsm4t(uint32_t* r, uint32_t a) {
    asm volatile("ldmatrix.sync.aligned.m8n8.x4.trans.shared.b16 {%0,%1,%2,%3}, [%4];"
                 : "=r"(r[0]), "=r"(r[1]), "=r"(r[2]), "=r"(r[3]) : "r"(a));
}

__device__ __forceinline__ void mma16816(float* c, const uint32_t* a, const uint32_t* b) {
    asm volatile(
        "mma.sync.aligned.m16n8k16.row.col.f32.f16.f16.f32 "
        "{%0,%1,%2,%3}, {%4,%5,%6,%7}, {%8,%9}, {%0,%1,%2,%3};"
        : "+f"(c[0]), "+f"(c[1]), "+f"(c[2]), "+f"(c[3])
        : "r"(a[0]), "r"(a[1]), "r"(a[2]), "r"(a[3]), "r"(b[0]), "r"(b[1]));
}

// ---------------- epilogue transforms ---------------------------------------
// TF: 0=raw 2=h(resid silu) 5=dz1 (fp16 dp/g1 inputs)
template <int TF>
__device__ __forceinline__ float2 xf(float v0, float v1, int R, int C,
    const __half* __restrict__ Ahi, const __half* __restrict__ Alo,
    const float* __restrict__ bias,
    const __half* __restrict__ eh0, const __half* __restrict__ eh1)
{
    if (TF == 0) return make_float2(v0, v1);
    if (TF == 5) {
        const size_t idx = (size_t)R * 256 + C;
        __half2 hd = *reinterpret_cast<const __half2*>(eh0 + idx);   // dp
        __half2 hg = *reinterpret_cast<const __half2*>(eh1 + idx);   // silu'(z1)
        float dh0 = __half2float(hd.x) + v0, dh1 = __half2float(hd.y) + v1;
        return make_float2(dh0 * __half2float(hg.x), dh1 * __half2float(hg.y));
    }
    // TF == 2
    float z0 = v0 + bias[C], z1v = v1 + bias[C + 1];
    float s0 = sigm(z0), s1 = sigm(z1v);
    __half2 ah = *reinterpret_cast<const __half2*>(Ahi + (size_t)R * 256 + C);
    __half2 al = *reinterpret_cast<const __half2*>(Alo + (size_t)R * 256 + C);
    float a0 = __half2float(ah.x) + __half2float(al.x);
    float a1 = __half2float(ah.y) + __half2float(al.y);
    return make_float2(a0 + z0 * s0, a1 + z1v * s1);
}

#define EPI_ARGS float (&acc)[4][4][4], char* sm, int m0, int n0, int warpR, int warpC, \
    int lane, int tid, const __half* __restrict__ Ahi, \
    const __half* __restrict__ Alo, const float* __restrict__ bias, \
    const __half* __restrict__ eh0, const __half* __restrict__ eh1

// normal-layout fp16 hi/lo store, smem-staged, coalesced.
// WLO=false: stage lo (for biasN) but skip its global store (dead array).
template <int TF, bool WLO>
__device__ __forceinline__ void passN(EPI_ARGS,
    __half* __restrict__ ohi, __half* __restrict__ olo)
{
    __syncthreads();
    uint32_t* s0 = (uint32_t*)sm;
    uint32_t* s1 = (uint32_t*)(sm + 34816);
    #pragma unroll
    for (int mt = 0; mt < 4; ++mt)
        #pragma unroll
        for (int h = 0; h < 2; ++h) {
            const int rl = warpR * 64 + mt * 16 + (lane >> 2) + h * 8;
            const int R = m0 + rl;
            #pragma unroll
            for (int nt = 0; nt < 4; ++nt) {
                const int cl = warpC * 32 + nt * 8 + 2 * (lane & 3);
                float2 t = xf<TF>(acc[mt][nt][2 * h], acc[mt][nt][2 * h + 1],
                                  R, n0 + cl, Ahi, Alo, bias, eh0, eh1);
                __half bh0 = __float2half_rn(t.x), bh1 = __float2half_rn(t.y);
                float l0 = t.x - __half2float(bh0);
                float l1 = t.y - __half2float(bh1);
                const int w = rl * 68 + (cl >> 1);
                s0[w] = (uint32_t)__half_as_ushort(bh0)
                      | ((uint32_t)__half_as_ushort(bh1) << 16);
                s1[w] = pack2h(l0, l1);
            }
        }
    __syncthreads();
    #pragma unroll
    for (int it = 0; it < 8; ++it) {
        const int row = it * 16 + (tid >> 4), seg = tid & 15;
        uint4 vh = *(uint4*)(sm + row * 272 + seg * 16);
        *(uint4*)(ohi + (size_t)(m0 + row) * 256 + n0 + seg * 8) = vh;
        if (WLO) {
            uint4 vl = *(uint4*)(sm + 34816 + row * 272 + seg * 16);
            *(uint4*)(olo + (size_t)(m0 + row) * 256 + n0 + seg * 8) = vl;
        }
    }
}

// bias-grad partials from N staging (hi+lo): column sums over 128 tokens.
__device__ __forceinline__ void biasN(char* sm, int m0, int n0, int tid,
                                      float* __restrict__ gbp)
{
    const int c = tid & 63, q = tid >> 6;          // colpair, row quarter
    const uint32_t* s0 = (const uint32_t*)sm;
    const uint32_t* s1 = (const uint32_t*)(sm + 34816);
    float se = 0.f, so = 0.f;
    #pragma unroll 8
    for (int r = q * 32; r < q * 32 + 32; ++r) {
        uint32_t w0 = s0[r * 68 + c], w1 = s1[r * 68 + c];
        __half2 a = *(const __half2*)&w0;
        __half2 b = *(const __half2*)&w1;
        se += __half2float(a.x) + __half2float(b.x);
        so += __half2float(a.y) + __half2float(b.y);
    }
    float* tmp = (float*)(sm + 70656);
    tmp[q * 128 + c * 2]     = se;
    tmp[q * 128 + c * 2 + 1] = so;
    __syncthreads();
    if (tid < 128)
        gbp[(m0 >> 7) * 256 + n0 + tid] =
            tmp[tid] + tmp[128 + tid] + tmp[256 + tid] + tmp[384 + tid];
}

// copy fp16 from s0 staging (272B stride) to global
__device__ __forceinline__ void copyH(char* sm, int m0, int n0, int tid,
                                      __half* __restrict__ o)
{
    #pragma unroll
    for (int it = 0; it < 8; ++it) {
        const int row = it * 16 + (tid >> 4), seg = tid & 15;
        uint4 v = *(uint4*)(sm + row * 272 + seg * 16);
        *(uint4*)(o + (size_t)(m0 + row) * 256 + n0 + seg * 8) = v;
    }
}

// store fp32 pass (reads 528B-stride staging)
__device__ __forceinline__ void storeF(char* sm, int m0, int n0, int tid,
                                       float* __restrict__ f0)
{
    #pragma unroll
    for (int it = 0; it < 16; ++it) {
        const int row = it * 8 + (tid >> 5), seg = tid & 31;
        uint4 v = *(uint4*)(sm + row * 528 + seg * 16);
        *(uint4*)(f0 + (size_t)(m0 + row) * 256 + n0 + seg * 4) = v;
    }
}

// fp32 store, smem-staged, with transform
template <int TF>
__device__ __forceinline__ void passF(EPI_ARGS, float* __restrict__ f0)
{
    __syncthreads();
    #pragma unroll
    for (int mt = 0; mt < 4; ++mt)
        #pragma unroll
        for (int h = 0; h < 2; ++h) {
            const int rl = warpR * 64 + mt * 16 + (lane >> 2) + h * 8;
            const int R = m0 + rl;
            #pragma unroll
            for (int nt = 0; nt < 4; ++nt) {
                const int cl = warpC * 32 + nt * 8 + 2 * (lane & 3);
                float2 t = xf<TF>(acc[mt][nt][2 * h], acc[mt][nt][2 * h + 1],
                                  R, n0 + cl, Ahi, Alo, bias, eh0, eh1);
                *(float2*)(sm + rl * 528 + cl * 4) = t;
            }
        }
    __syncthreads();
    storeF(sm, m0, n0, tid, f0);
}

// combined transform: stage fp16 (g1 or dp) to s0, leave fp16-source in acc.
// IS_DZ2=0: stage silu'(z), acc=h (residual silu). IS_DZ2=1: stage d, acc=dz2.
template <int IS_DZ2>
__device__ __forceinline__ void combinedTF(float (&acc)[4][4][4], char* sm,
    int m0, int n0, int warpR, int warpC, int lane,
    const __half* __restrict__ Ahi, const __half* __restrict__ Alo,
    const float* __restrict__ bias, const __half* __restrict__ valsh,
    const float* __restrict__ alr_)
{
    __syncthreads();
    uint32_t* s0 = (uint32_t*)sm;
    #pragma unroll
    for (int mt = 0; mt < 4; ++mt)
        #pragma unroll
        for (int h = 0; h < 2; ++h) {
            const int rl = warpR * 64 + mt * 16 + (lane >> 2) + h * 8;
            const int R = m0 + rl;
            float cf = 0.f;
            if (IS_DZ2) cf = alr_[R] * 0.0078125f;
            #pragma unroll
            for (int nt = 0; nt < 4; ++nt) {
                const int cl = warpC * 32 + nt * 8 + 2 * (lane & 3);
                const int C = n0 + cl;
                const size_t idx = (size_t)R * 256 + C;
                float z0 = acc[mt][nt][2 * h]     + bias[C];
                float z1v = acc[mt][nt][2 * h + 1] + bias[C + 1];
                float s0v = sigm(z0), s1v = sigm(z1v);
                __half2 ah = *(const __half2*)(Ahi + idx);
                __half2 al = *(const __half2*)(Alo + idx);
                float a0 = __half2float(ah.x) + __half2float(al.x);
                float a1 = __half2float(ah.y) + __half2float(al.y);
                float h0 = a0 + z0 * s0v, h1v = a1 + z1v * s1v;
                const int w = rl * 68 + (cl >> 1);
                if (!IS_DZ2) {
                    float g0 = s0v * (1.f + z0 * (1.f - s0v));
                    float g1 = s1v * (1.f + z1v * (1.f - s1v));
                    s0[w] = pack2h(g0, g1);
                    acc[mt][nt][2 * h] = h0;
                    acc[mt][nt][2 * h + 1] = h1v;
                } else {
                    __half2 e = *(const __half2*)(valsh + idx);
                    float d0 = cf * (h0 - __half2float(e.x));
                    float d1 = cf * (h1v - __half2float(e.y));
                    s0[w] = pack2h(d0, d1);
                    acc[mt][nt][2 * h]     = d0 * s0v * (1.f + z0 * (1.f - s0v));
                    acc[mt][nt][2 * h + 1] = d1 * s1v * (1.f + z1v * (1.f - s1v));
                }
            }
        }
    __syncthreads();
}

// ---------------- mma.sync GEMM: C[128 x 128] tile, single-pass fp16 --------
// 3-buffer cp.async pipeline (wait_group 1 => one extra chunk in flight)
enum { M_PROJ3 = 0, M_FWD_KT, M_FWD_Q, M_FWD_OUT, M_DZ2, M_DZ1 };

#define SMEM_BYTES 81920
#define BUF_MM 20480   // Ah(10240) Bh(10240)

struct MMArgs {
    const __half *Ah, *Al, *Bh;
    const float *bias, *alr;
    const __half *valsh, *eh0, *eh1;
    float *f0, *gbp;
    __half *f0h;
    __half *ohi, *olo, *o2h, *o2l, *o3h;
};

template <int MODE>
__global__ __launch_bounds__(256, 2) void mm_k(const MMArgs a)
{
    extern __shared__ char sm[];
    const int tid = threadIdx.x, lane = tid & 31, wid = tid >> 5;
    const int warpR = wid >> 2, warpC = wid & 3;
    const int m0 = blockIdx.y * 128;
    const int n0 = (MODE == M_PROJ3 ? (blockIdx.x & 1) * 128 : blockIdx.x * 128);
    const uint32_t sb = smem_u32(sm);

    const __half *Ahi = a.Ah, *Bhi = a.Bh;
    int slot = 0;
    if (MODE == M_PROJ3) {
        slot = blockIdx.x >> 1;
        Bhi = a.Bh + (size_t)slot * DD;
    }

    float acc[4][4][4];
    #pragma unroll
    for (int i = 0; i < 4; ++i)
        #pragma unroll
        for (int j = 0; j < 4; ++j)
            #pragma unroll
            for (int e = 0; e < 4; ++e) acc[i][j][e] = 0.f;

    const uint32_t aoff = (uint32_t)((((lane & 7) + ((lane >> 3) & 1) * 8)) * 80
                                     + (lane >> 4) * 16);
    const uint32_t boff4 = (uint32_t)(((lane & 7) + (lane >> 4) * 8) * 80
                                      + ((lane >> 3) & 1) * 16);

    #define LOAD_CHUNK(ck, buf) do {                                           \
        const int k0_ = (ck) * 32;                                             \
        const uint32_t sbb_ = sb + (buf) * BUF_MM;                             \
        _Pragma("unroll")                                                      \
        for (int rep = 0; rep < 2; ++rep) {                                    \
            const int id = tid + rep * 256;                                    \
            const int row = id >> 2, seg = id & 3;                             \
            const uint32_t so = row * 80 + seg * 16;                           \
            const long ga = (long)(m0 + row) * 256 + k0_ + seg * 8;            \
            const long gbx = (long)(n0 + row) * 256 + k0_ + seg * 8;           \
            cp16(sbb_ + so,          Ahi + ga);                                \
            cp16(sbb_ + 10240 + so,  Bhi + gbx);                               \
        }                                                                      \
        cp_commit();                                                           \
    } while (0)

    LOAD_CHUNK(0, 0);
    LOAD_CHUNK(1, 1);
    #pragma unroll 1
    for (int ck = 0; ck < 8; ++ck) {
        cp_wait<1>();
        __syncthreads();
        if (ck + 2 < 8) LOAD_CHUNK(ck + 2, (ck + 2) % 3); else cp_commit();
        const uint32_t sbb = sb + (ck % 3) * BUF_MM;
        #pragma unroll
        for (int step = 0; step < 2; ++step) {
            uint32_t av[4][4], bh[4][2];
            #pragma unroll
            for (int mt = 0; mt < 4; ++mt)
                ldsm4(av[mt], sbb + (warpR * 64 + mt * 16) * 80 + step * 32 + aoff);
            #pragma unroll
            for (int ntp = 0; ntp < 2; ++ntp)
                ldsm4(&bh[2 * ntp][0],
                      sbb + 10240 + (warpC * 32 + ntp * 16) * 80 + step * 32 + boff4);
            #pragma unroll
            for (int mt = 0; mt < 4; ++mt)
                #pragma unroll
                for (int nt = 0; nt < 4; ++nt)
                    mma16816(acc[mt][nt], av[mt], bh[nt]);
        }
    }
    #undef LOAD_CHUNK

    #define EPI acc, sm, m0, n0, warpR, warpC, lane, tid, a.Ah, a.Al, a.bias, a.eh0, a.eh1
    if (MODE == M_PROJ3) {
        if (slot == 2)      passN<0, false>(EPI, a.o3h, nullptr); // values fp16
        else if (slot == 1) passN<0, true>(EPI, a.o2h, a.o2l);    // queries
        else                passN<0, true>(EPI, a.ohi, a.olo);    // keys
    } else if (MODE == M_FWD_KT) {
        combinedTF<0>(acc, sm, m0, n0, warpR, warpC, lane, a.Ah, a.Al, a.bias,
                      nullptr, nullptr);
        copyH(sm, m0, n0, tid, a.f0h);                            // g1 = silu'(z1)
        passN<0, true>(EPI, a.ohi, a.olo);                        // h1
    } else if (MODE == M_FWD_Q) {
        passN<2, true>(EPI, a.ohi, a.olo);
    } else if (MODE == M_FWD_OUT) {
        passF<2>(EPI, a.f0);
    } else if (MODE == M_DZ2) {
        combinedTF<1>(acc, sm, m0, n0, warpR, warpC, lane, a.Ah, a.Al, a.bias,
                      a.valsh, a.alr);
        copyH(sm, m0, n0, tid, a.f0h);                            // dp fp16
        passN<0, false>(EPI, a.ohi, nullptr);                     // dz2 (hi only)
        biasN(sm, m0, n0, tid, a.gbp);                            // layer-1 bias partials
    } else {                                                      // M_DZ1
        passN<5, false>(EPI, a.ohi, nullptr);                     // dz1 (hi only)
        biasN(sm, m0, n0, tid, a.gbp);                            // layer-0 bias partials
    }
    #undef EPI
}

// ---------------- weight-grad GEMM via ldmatrix.trans on normal layout ------
// C[k1,k2] += sum_n Ah[n][k1]*Bh[n][k2]  (single-pass fp16 hi), 3-buffer pipe.
// grid (2, 2, 128): x=n-tile, y=m-tile, z: [0,64)=h1ᵀ@dz2, [64,128)=keysᵀ@dz1
#define BUF_WG 17408   // Ah(8704) Bh(8704)

struct WGArgs {
    const __half *A1h, *B1h;
    const __half *A2h, *B2h;
    float* part;
};

__global__ __launch_bounds__(256, 2) void wg_k(const WGArgs a)
{
    extern __shared__ char sm[];
    const int tid = threadIdx.x, lane = tid & 31, wid = tid >> 5;
    const int warpR = wid >> 2, warpC = wid & 3;
    const int m0 = blockIdx.y * 128, n0 = blockIdx.x * 128;
    const int gemm = blockIdx.z >> 6;
    const long tokbase = (long)(blockIdx.z & 63) * 512;
    const uint32_t sb = smem_u32(sm);

    const __half* Ah = gemm ? a.A2h : a.A1h;
    const __half* Bh = gemm ? a.B2h : a.B1h;

    float acc[4][4][4];
    #pragma unroll
    for (int i = 0; i < 4; ++i)
        #pragma unroll
        for (int j = 0; j < 4; ++j)
            #pragma unroll
            for (int e = 0; e < 4; ++e) acc[i][j][e] = 0.f;

    const uint32_t atoff = (uint32_t)((((lane >> 4) & 1) * 8 + (lane & 7)) * 272
                                      + ((lane >> 3) & 1) * 16);
    const uint32_t btoff4 = (uint32_t)(((((lane >> 3) & 1) * 8 + (lane & 7))) * 272
                                       + (lane >> 4) * 16);

    #define WLOAD(ck, buf) do {                                                \
        const long t0 = tokbase + (long)(ck) * 32;                             \
        const uint32_t sbb_ = sb + (buf) * BUF_WG;                             \
        _Pragma("unroll")                                                      \
        for (int rep = 0; rep < 2; ++rep) {                                    \
            const int id = tid + rep * 256;                                    \
            const int row = id >> 4, seg = id & 15;                            \
            const uint32_t so = row * 272 + seg * 16;                          \
            const long gA = (t0 + row) * 256 + m0 + seg * 8;                   \
            const long gB = (t0 + row) * 256 + n0 + seg * 8;                   \
            cp16(sbb_ + so,         Ah + gA);                                  \
            cp16(sbb_ + 8704 + so,  Bh + gB);                                  \
        }                                                                      \
        cp_commit();                                                           \
    } while (0)

    WLOAD(0, 0);
    WLOAD(1, 1);
    #pragma unroll 1
    for (int ck = 0; ck < 16; ++ck) {
        cp_wait<1>();
        __syncthreads();
        if (ck + 2 < 16) WLOAD(ck + 2, (ck + 2) % 3); else cp_commit();
        const uint32_t sbb = sb + (ck % 3) * BUF_WG;
        #pragma unroll
        for (int step = 0; step < 2; ++step) {
            const uint32_t ks = step * 16 * 272;
            uint32_t av[4][4], bh[4][2];
            #pragma unroll
            for (int mt = 0; mt < 4; ++mt)
                ldsm4t(av[mt], sbb + ks + atoff + (warpR * 64 + mt * 16) * 2);
            #pragma unroll
            for (int ntp = 0; ntp < 2; ++ntp) {
                const uint32_t nb = (warpC * 32 + ntp * 16) * 2;
                ldsm4t(&bh[2 * ntp][0], sbb + 8704 + ks + btoff4 + nb);
            }
            #pragma unroll
            for (int mt = 0; mt < 4; ++mt)
                #pragma unroll
                for (int nt = 0; nt < 4; ++nt)
                    mma16816(acc[mt][nt], av[mt], bh[nt]);
        }
    }
    #undef WLOAD

    passF<0>(acc, sm, m0, n0, warpR, warpC, lane, tid, nullptr, nullptr,
             nullptr, nullptr, nullptr, a.part + (size_t)blockIdx.z * DD);
}

// ---------------- fused prep: x split + adaptive lr + weight prep -----------
// blocks [0, NTOK/8): xsplit+alr.  blocks [NTOK/8, NTOK/8 + 6*DD/256): wprep.
__global__ void prep_k(const float* __restrict__ x, const float* __restrict__ Wlr,
                       const float* __restrict__ blr,
                       const float* __restrict__ Wk, const float* __restrict__ Wq,
                       const float* __restrict__ Wv, const float* __restrict__ Ws,
                       __half* __restrict__ xh, float* __restrict__ alr,
                       __half* __restrict__ wh)
{
    const int b = blockIdx.x;
    if (b < NTOK / 8) {
        const int warp = threadIdx.x >> 5, lane = threadIdx.x & 31;
        const long tok = (long)b * 8 + warp;
        const float* xr = x + tok * 256 + lane * 8;
        float4 va = *(const float4*)xr;
        float4 vb = *(const float4*)(xr + 4);
        float v[8] = {va.x, va.y, va.z, va.w, vb.x, vb.y, vb.z, vb.w};
        const float* wr = Wlr + lane * 8;
        float dot = 0.f;
        ushort hs[8];
        #pragma unroll
        for (int j = 0; j < 8; ++j) {
            dot += v[j] * wr[j];
            hs[j] = __half_as_ushort(__float2half_rn(v[j]));
        }
        *(uint4*)(xh + tok * 256 + lane * 8) = *(uint4*)hs;
        #pragma unroll
        for (int o = 16; o > 0; o >>= 1) dot += __shfl_xor_sync(0xffffffffu, dot, o);
        if (lane == 0) alr[tok] = 0.1f * sigm(dot + blr[0]);
    } else {
        // slots: 0=Wk^T 1=Wq^T 2=Wv^T 3=W0^T 4=W1^T 5=W1
        const int idx = (b - NTOK / 8) * 256 + threadIdx.x;
        const int slot = idx >> 16;
        const int r = (idx >> 8) & 255;
        const int c = idx & 255;
        float v;
        if      (slot == 0) v = Wk[c * 256 + r];
        else if (slot == 1) v = Wq[c * 256 + r];
        else if (slot == 2) v = Wv[c * 256 + r];
        else if (slot == 3) v = Ws[c * 256 + r];
        else if (slot == 4) v = Ws[DD + c * 256 + r];
        else                v = Ws[DD + r * 256 + c];
        wh[idx] = __float2half_rn(v);
    }
}

// ---- fused reduce + AdamW: -grads to out, fp16 transposed updated weights --
// part slices 0..63 = h1^T@dz2 (gW1/layer1); 64..127 = keys^T@dz1 (gW0/layer0)
__global__ void adamw_f(const float* __restrict__ Ws, const float* __restrict__ bs,
                        const float* __restrict__ part, const float* __restrict__ gbp,
                        __half* __restrict__ nwth, float* __restrict__ nb,
                        float* __restrict__ out)
{
    const int idx = blockIdx.x * 256 + threadIdx.x;
    const float decay = 1.0f - LRc * WDc;
    if (idx < 2 * DD) {
        const int layer = idx >> 16;
        const int j = idx & 65535;
        const int zbase = (layer == 0) ? 64 : 0;
        float g = 0.0f;
        #pragma unroll 4
        for (int z = 0; z < 64; ++z) g += part[(size_t)(zbase + z) * DD + j];
        out[ND + idx] = -g;
        const float nw = Ws[idx] * decay - LRc * g / (fabsf(g) + EPSc);
        const int k = (idx >> 8) & 255;
        const int n = idx & 255;
        nwth[(long)layer * DD + n * 256 + k] = __float2half_rn(nw);
    } else if (idx < 2 * DD + 2 * D) {
        const int b = idx - 2 * DD;
        const int layer = b >> 8;
        const int j = b & 255;
        const float* p = gbp + (size_t)layer * 65536;
        float g = 0.f;
        for (int mt = 0; mt < 256; ++mt) g += p[mt * 256 + j];
        out[ND + 2 * DD + b] = -g;
        nb[b] = bs[b] * decay - LRc * g / (fabsf(g) + EPSc);
    }
}

// ---------------------------------------------------------------------------
extern "C" void kernel_launch(void* const* d_in, const int* in_sizes, int n_in,
                              void* d_out, int out_size)
{
    const float* x   = (const float*)d_in[0];
    const float* Wk  = (const float*)d_in[1];
    const float* Wq  = (const float*)d_in[2];
    const float* Wv  = (const float*)d_in[3];
    const float* Wlr = (const float*)d_in[4];
    const float* blr = (const float*)d_in[5];
    const float* Ws  = (const float*)d_in[6];
    const float* bs  = (const float*)d_in[7];
    float* out = (float*)d_out;

    #define SYM(T, v, s) T* v; cudaGetSymbolAddress((void**)&v, s)
    SYM(__half, xbh, g_xbh);
    SYM(__half, keysh, g_keysh); SYM(__half, keysl, g_keysl);
    SYM(__half, qh, g_qh);     SYM(__half, ql, g_ql);
    SYM(__half, h1h, g_h1h);   SYM(__half, h1l, g_h1l);
    SYM(__half, dz2h, g_dz2h);
    SYM(__half, dz1h, g_dz1h);
    SYM(__half, h1qh, g_h1qh); SYM(__half, h1ql, g_h1ql);
    SYM(__half, g1, g_g1);     SYM(__half, dp, g_dp);
    SYM(__half, valh, g_valh);
    SYM(__half, wbh, g_wbh);
    SYM(__half, nwth, g_nwth);
    SYM(float, part, g_part); SYM(float, gbp, g_gbp);
    SYM(float, nb, g_nb); SYM(float, alr, g_alr);
    #undef SYM

    #define SETSM(M) cudaFuncSetAttribute(mm_k<M>, \
        cudaFuncAttributeMaxDynamicSharedMemorySize, SMEM_BYTES)
    SETSM(M_PROJ3); SETSM(M_FWD_KT); SETSM(M_FWD_Q);
    SETSM(M_FWD_OUT); SETSM(M_DZ2); SETSM(M_DZ1);
    #undef SETSM
    cudaFuncSetAttribute(wg_k, cudaFuncAttributeMaxDynamicSharedMemorySize, SMEM_BYTES);

    // fused prep: x->fp16 + alr + weight transposes
    prep_k<<<NTOK / 8 + 6 * DD / 256, 256>>>(x, Wlr, blr, Wk, Wq, Wv, Ws,
                                             xbh, alr, wbh);

    MMArgs a = {};
    // fused projections: keys, queries, values
    a.Ah = xbh; a.Bh = wbh;
    a.ohi = keysh; a.olo = keysl; a.o2h = qh; a.o2l = ql; a.o3h = valh;
    mm_k<M_PROJ3><<<dim3(6, 256), 256, SMEM_BYTES>>>(a);

    // forward on keys: g1=silu'(z1) fp16 + h1 (fp16 pair)
    a = {};
    a.Ah = keysh; a.Al = keysl; a.Bh = wbh + 3 * DD;
    a.bias = bs; a.f0h = g1; a.ohi = h1h; a.olo = h1l;
    mm_k<M_FWD_KT><<<dim3(2, 256), 256, SMEM_BYTES>>>(a);

    // dz2 + dp(fp16) + layer-1 bias partials (z2 recomputed in epilogue)
    a = {};
    a.Ah = h1h; a.Al = h1l; a.Bh = wbh + 4 * DD;
    a.bias = bs + D; a.valsh = valh; a.alr = alr; a.f0h = dp;
    a.ohi = dz2h; a.gbp = gbp + 65536;
    mm_k<M_DZ2><<<dim3(2, 256), 256, SMEM_BYTES>>>(a);

    // dz1 = (dp + dz2 @ W1^T) * silu'(z1)  + layer-0 bias partials
    a = {};
    a.Ah = dz2h; a.Bh = wbh + 5 * DD;
    a.eh0 = dp; a.eh1 = g1; a.ohi = dz1h; a.gbp = gbp;
    mm_k<M_DZ1><<<dim3(2, 256), 256, SMEM_BYTES>>>(a);

    // weight grads, single-pass hi (split-K 64 each, 512 tokens/slice)
    WGArgs w = {};
    w.A1h = h1h;   w.B1h = dz2h;
    w.A2h = keysh; w.B2h = dz1h;
    w.part = part;
    wg_k<<<dim3(2, 2, 128), 256, SMEM_BYTES>>>(w);

    // fused: split-K reduce + bias reduce + AdamW + emit -grads
    adamw_f<<<(2 * DD + 2 * D + 255) / 256, 256>>>(Ws, bs, part, gbp,
                                                   nwth, nb, out);

    // retrieved = forward(queries) with updated weights
    a = {};
    a.Ah = qh; a.Al = ql; a.Bh = nwth;
    a.bias = nb; a.ohi = h1qh; a.olo = h1ql;
    mm_k<M_FWD_Q><<<dim3(2, 256), 256, SMEM_BYTES>>>(a);

    a = {};
    a.Ah = h1qh; a.Al = h1ql; a.Bh = nwth + DD;
    a.bias = nb + D; a.f0 = out;
    mm_k<M_FWD_OUT><<<dim3(2, 256), 256, SMEM_BYTES>>>(a);
}

// round 17
// speedup vs baseline: 1.5126x; 1.5126x over previous
#include <cuda_runtime.h>
#include <cuda_fp16.h>
#include <math.h>
#include <stdint.h>

#define D      256
#define NTOK   32768
#define ND     (NTOK * D)
#define DD     (D * D)
#define LRc    1e-3f
#define WDc    1e-2f
#define EPSc   1e-8f

// ---------------- scratch (device globals: allocation-free) ----------------
__device__ __half g_xbh[ND];
__device__ __half g_keysh[ND], g_keysl[ND];
__device__ __half g_qh[ND],   g_ql[ND];
__device__ __half g_h1h[ND],  g_h1l[ND];
__device__ __half g_dz2h[ND];
__device__ __half g_dz1h[ND];
__device__ __half g_h1qh[ND], g_h1ql[ND];
__device__ __half g_g1[ND], g_dp[ND];          // fp16 intermediates
__device__ __half g_wbh[6 * DD];
__device__ __half g_nwth[2 * DD];
__device__ float g_values[ND];
__device__ float g_part[64 * DD];
__device__ float g_gbp[2 * 256 * 256];
__device__ float g_nb[2 * D], g_alr[NTOK];

// fast sigmoid: MUFU.EX2 + MUFU.RCP path (~4 instrs)
__device__ __forceinline__ float sigm(float z) {
    return __fdividef(1.0f, 1.0f + __expf(-z));
}

__device__ __forceinline__ uint32_t pack2h(float a, float b) {
    return (uint32_t)__half_as_ushort(__float2half_rn(a))
         | ((uint32_t)__half_as_ushort(__float2half_rn(b)) << 16);
}

__device__ __forceinline__ uint32_t smem_u32(const void* p) {
    uint32_t a;
    asm("{ .reg .u64 t; cvta.to.shared.u64 t, %1; cvt.u32.u64 %0, t; }"
        : "=r"(a) : "l"(p));
    return a;
}

__device__ __forceinline__ void cp16(uint32_t dst, const void* src) {
    asm volatile("cp.async.cg.shared.global [%0], [%1], 16;"
                 :: "r"(dst), "l"(src) : "memory");
}
__device__ __forceinline__ void cp_commit() {
    asm volatile("cp.async.commit_group;" ::: "memory");
}
template <int N>
__device__ __forceinline__ void cp_wait() {
    asm volatile("cp.async.wait_group %0;" :: "n"(N) : "memory");
}

__device__ __forceinline__ void ldsm4(uint32_t* r, uint32_t a) {
    asm volatile("ldmatrix.sync.aligned.m8n8.x4.shared.b16 {%0,%1,%2,%3}, [%4];"
                 : "=r"(r[0]), "=r"(r[1]), "=r"(r[2]), "=r"(r[3]) : "r"(a));
}
__device__ __forceinline__ void ldsm4t(uint32_t* r, uint32_t a) {
    asm volatile("ldmatrix.sync.aligned.m8n8.x4.trans.shared.b16 {%0,%1,%2,%3}, [%4];"
                 : "=r"(r[0]), "=r"(r[1]), "=r"(r[2]), "=r"(r[3]) : "r"(a));
}

__device__ __forceinline__ void mma16816(float* c, const uint32_t* a, const uint32_t* b) {
    asm volatile(
        "mma.sync.aligned.m16n8k16.row.col.f32.f16.f16.f32 "
        "{%0,%1,%2,%3}, {%4,%5,%6,%7}, {%8,%9}, {%0,%1,%2,%3};"
        : "+f"(c[0]), "+f"(c[1]), "+f"(c[2]), "+f"(c[3])
        : "r"(a[0]), "r"(a[1]), "r"(a[2]), "r"(a[3]), "r"(b[0]), "r"(b[1]));
}

// ---------------- epilogue transforms ---------------------------------------
// TF: 0=raw 2=h(resid silu) 5=dz1 (fp16 dp/g1 inputs)
template <int TF>
__device__ __forceinline__ float2 xf(float v0, float v1, int R, int C,
    const __half* __restrict__ Ahi, const __half* __restrict__ Alo,
    const float* __restrict__ bias,
    const __half* __restrict__ eh0, const __half* __restrict__ eh1)
{
    if (TF == 0) return make_float2(v0, v1);
    if (TF == 5) {
        const size_t idx = (size_t)R * 256 + C;
        __half2 hd = *reinterpret_cast<const __half2*>(eh0 + idx);   // dp
        __half2 hg = *reinterpret_cast<const __half2*>(eh1 + idx);   // silu'(z1)
        float dh0 = __half2float(hd.x) + v0, dh1 = __half2float(hd.y) + v1;
        return make_float2(dh0 * __half2float(hg.x), dh1 * __half2float(hg.y));
    }
    // TF == 2
    float z0 = v0 + bias[C], z1v = v1 + bias[C + 1];
    float s0 = sigm(z0), s1 = sigm(z1v);
    __half2 ah = *reinterpret_cast<const __half2*>(Ahi + (size_t)R * 256 + C);
    __half2 al = *reinterpret_cast<const __half2*>(Alo + (size_t)R * 256 + C);
    float a0 = __half2float(ah.x) + __half2float(al.x);
    float a1 = __half2float(ah.y) + __half2float(al.y);
    return make_float2(a0 + z0 * s0, a1 + z1v * s1);
}

#define EPI_ARGS float (&acc)[4][4][4], char* sm, int m0, int n0, int warpR, int warpC, \
    int lane, int tid, const __half* __restrict__ Ahi, \
    const __half* __restrict__ Alo, const float* __restrict__ bias, \
    const __half* __restrict__ eh0, const __half* __restrict__ eh1

// normal-layout fp16 hi/lo store, smem-staged, coalesced.
// WLO=false: stage lo (for biasN) but skip its global store (dead array).
template <int TF, bool WLO>
__device__ __forceinline__ void passN(EPI_ARGS,
    __half* __restrict__ ohi, __half* __restrict__ olo)
{
    __syncthreads();
    uint32_t* s0 = (uint32_t*)sm;
    uint32_t* s1 = (uint32_t*)(sm + 34816);
    #pragma unroll
    for (int mt = 0; mt < 4; ++mt)
        #pragma unroll
        for (int h = 0; h < 2; ++h) {
            const int rl = warpR * 64 + mt * 16 + (lane >> 2) + h * 8;
            const int R = m0 + rl;
            #pragma unroll
            for (int nt = 0; nt < 4; ++nt) {
                const int cl = warpC * 32 + nt * 8 + 2 * (lane & 3);
                float2 t = xf<TF>(acc[mt][nt][2 * h], acc[mt][nt][2 * h + 1],
                                  R, n0 + cl, Ahi, Alo, bias, eh0, eh1);
                __half bh0 = __float2half_rn(t.x), bh1 = __float2half_rn(t.y);
                float l0 = t.x - __half2float(bh0);
                float l1 = t.y - __half2float(bh1);
                const int w = rl * 68 + (cl >> 1);
                s0[w] = (uint32_t)__half_as_ushort(bh0)
                      | ((uint32_t)__half_as_ushort(bh1) << 16);
                s1[w] = pack2h(l0, l1);
            }
        }
    __syncthreads();
    #pragma unroll
    for (int it = 0; it < 8; ++it) {
        const int row = it * 16 + (tid >> 4), seg = tid & 15;
        uint4 vh = *(uint4*)(sm + row * 272 + seg * 16);
        *(uint4*)(ohi + (size_t)(m0 + row) * 256 + n0 + seg * 8) = vh;
        if (WLO) {
            uint4 vl = *(uint4*)(sm + 34816 + row * 272 + seg * 16);
            *(uint4*)(olo + (size_t)(m0 + row) * 256 + n0 + seg * 8) = vl;
        }
    }
}

// bias-grad partials from N staging (hi+lo): column sums over 128 tokens.
__device__ __forceinline__ void biasN(char* sm, int m0, int n0, int tid,
                                      float* __restrict__ gbp)
{
    const int c = tid & 63, q = tid >> 6;          // colpair, row quarter
    const uint32_t* s0 = (const uint32_t*)sm;
    const uint32_t* s1 = (const uint32_t*)(sm + 34816);
    float se = 0.f, so = 0.f;
    #pragma unroll 8
    for (int r = q * 32; r < q * 32 + 32; ++r) {
        uint32_t w0 = s0[r * 68 + c], w1 = s1[r * 68 + c];
        __half2 a = *(const __half2*)&w0;
        __half2 b = *(const __half2*)&w1;
        se += __half2float(a.x) + __half2float(b.x);
        so += __half2float(a.y) + __half2float(b.y);
    }
    float* tmp = (float*)(sm + 70656);
    tmp[q * 128 + c * 2]     = se;
    tmp[q * 128 + c * 2 + 1] = so;
    __syncthreads();
    if (tid < 128)
        gbp[(m0 >> 7) * 256 + n0 + tid] =
            tmp[tid] + tmp[128 + tid] + tmp[256 + tid] + tmp[384 + tid];
}

// copy fp16 from s0 staging (272B stride) to global
__device__ __forceinline__ void copyH(char* sm, int m0, int n0, int tid,
                                      __half* __restrict__ o)
{
    #pragma unroll
    for (int it = 0; it < 8; ++it) {
        const int row = it * 16 + (tid >> 4), seg = tid & 15;
        uint4 v = *(uint4*)(sm + row * 272 + seg * 16);
        *(uint4*)(o + (size_t)(m0 + row) * 256 + n0 + seg * 8) = v;
    }
}

// store fp32 pass (reads 528B-stride staging)
__device__ __forceinline__ void storeF(char* sm, int m0, int n0, int tid,
                                       float* __restrict__ f0)
{
    #pragma unroll
    for (int it = 0; it < 16; ++it) {
        const int row = it * 8 + (tid >> 5), seg = tid & 31;
        uint4 v = *(uint4*)(sm + row * 528 + seg * 16);
        *(uint4*)(f0 + (size_t)(m0 + row) * 256 + n0 + seg * 4) = v;
    }
}

// fp32 store, smem-staged, with transform
template <int TF>
__device__ __forceinline__ void passF(EPI_ARGS, float* __restrict__ f0)
{
    __syncthreads();
    #pragma unroll
    for (int mt = 0; mt < 4; ++mt)
        #pragma unroll
        for (int h = 0; h < 2; ++h) {
            const int rl = warpR * 64 + mt * 16 + (lane >> 2) + h * 8;
            const int R = m0 + rl;
            #pragma unroll
            for (int nt = 0; nt < 4; ++nt) {
                const int cl = warpC * 32 + nt * 8 + 2 * (lane & 3);
                float2 t = xf<TF>(acc[mt][nt][2 * h], acc[mt][nt][2 * h + 1],
                                  R, n0 + cl, Ahi, Alo, bias, eh0, eh1);
                *(float2*)(sm + rl * 528 + cl * 4) = t;
            }
        }
    __syncthreads();
    storeF(sm, m0, n0, tid, f0);
}

// combined transform: stage fp16 (g1 or dp) to s0, leave fp16-source in acc.
// IS_DZ2=0: stage silu'(z), acc=h (residual silu). IS_DZ2=1: stage d, acc=dz2.
template <int IS_DZ2>
__device__ __forceinline__ void combinedTF(float (&acc)[4][4][4], char* sm,
    int m0, int n0, int warpR, int warpC, int lane,
    const __half* __restrict__ Ahi, const __half* __restrict__ Alo,
    const float* __restrict__ bias, const float* __restrict__ vals,
    const float* __restrict__ alr_)
{
    __syncthreads();
    uint32_t* s0 = (uint32_t*)sm;
    #pragma unroll
    for (int mt = 0; mt < 4; ++mt)
        #pragma unroll
        for (int h = 0; h < 2; ++h) {
            const int rl = warpR * 64 + mt * 16 + (lane >> 2) + h * 8;
            const int R = m0 + rl;
            float cf = 0.f;
            if (IS_DZ2) cf = alr_[R] * 0.0078125f;
            #pragma unroll
            for (int nt = 0; nt < 4; ++nt) {
                const int cl = warpC * 32 + nt * 8 + 2 * (lane & 3);
                const int C = n0 + cl;
                const size_t idx = (size_t)R * 256 + C;
                float z0 = acc[mt][nt][2 * h]     + bias[C];
                float z1v = acc[mt][nt][2 * h + 1] + bias[C + 1];
                float s0v = sigm(z0), s1v = sigm(z1v);
                __half2 ah = *(const __half2*)(Ahi + idx);
                __half2 al = *(const __half2*)(Alo + idx);
                float a0 = __half2float(ah.x) + __half2float(al.x);
                float a1 = __half2float(ah.y) + __half2float(al.y);
                float h0 = a0 + z0 * s0v, h1v = a1 + z1v * s1v;
                const int w = rl * 68 + (cl >> 1);
                if (!IS_DZ2) {
                    float g0 = s0v * (1.f + z0 * (1.f - s0v));
                    float g1 = s1v * (1.f + z1v * (1.f - s1v));
                    s0[w] = pack2h(g0, g1);
                    acc[mt][nt][2 * h] = h0;
                    acc[mt][nt][2 * h + 1] = h1v;
                } else {
                    float2 e = *(const float2*)(vals + idx);
                    float d0 = cf * (h0 - e.x), d1 = cf * (h1v - e.y);
                    s0[w] = pack2h(d0, d1);
                    acc[mt][nt][2 * h]     = d0 * s0v * (1.f + z0 * (1.f - s0v));
                    acc[mt][nt][2 * h + 1] = d1 * s1v * (1.f + z1v * (1.f - s1v));
                }
            }
        }
    __syncthreads();
}

// ---------------- mma.sync GEMM: C[128 x 128] tile, single-pass fp16 --------
// 3-buffer cp.async pipeline (wait_group 1 => one extra chunk in flight)
enum { M_PROJ3 = 0, M_FWD_KT, M_FWD_Q, M_FWD_OUT, M_DZ2, M_DZ1 };

#define SMEM_BYTES 81920
#define BUF_MM 20480   // Ah(10240) Bh(10240)

struct MMArgs {
    const __half *Ah, *Al, *Bh;
    const float *bias, *vals, *alr;
    const __half *eh0, *eh1;
    float *f0, *gbp;
    __half *f0h;
    __half *ohi, *olo, *o2h, *o2l;
};

template <int MODE>
__global__ __launch_bounds__(256, 2) void mm_k(const MMArgs a)
{
    extern __shared__ char sm[];
    const int tid = threadIdx.x, lane = tid & 31, wid = tid >> 5;
    const int warpR = wid >> 2, warpC = wid & 3;
    const int m0 = blockIdx.y * 128;
    const int n0 = (MODE == M_PROJ3 ? (blockIdx.x & 1) * 128 : blockIdx.x * 128);
    const uint32_t sb = smem_u32(sm);

    const __half *Ahi = a.Ah, *Bhi = a.Bh;
    int slot = 0;
    if (MODE == M_PROJ3) {
        slot = blockIdx.x >> 1;
        Bhi = a.Bh + (size_t)slot * DD;
    }

    float acc[4][4][4];
    #pragma unroll
    for (int i = 0; i < 4; ++i)
        #pragma unroll
        for (int j = 0; j < 4; ++j)
            #pragma unroll
            for (int e = 0; e < 4; ++e) acc[i][j][e] = 0.f;

    const uint32_t aoff = (uint32_t)((((lane & 7) + ((lane >> 3) & 1) * 8)) * 80
                                     + (lane >> 4) * 16);
    const uint32_t boff4 = (uint32_t)(((lane & 7) + (lane >> 4) * 8) * 80
                                      + ((lane >> 3) & 1) * 16);

    #define LOAD_CHUNK(ck, buf) do {                                           \
        const int k0_ = (ck) * 32;                                             \
        const uint32_t sbb_ = sb + (buf) * BUF_MM;                             \
        _Pragma("unroll")                                                      \
        for (int rep = 0; rep < 2; ++rep) {                                    \
            const int id = tid + rep * 256;                                    \
            const int row = id >> 2, seg = id & 3;                             \
            const uint32_t so = row * 80 + seg * 16;                           \
            const long ga = (long)(m0 + row) * 256 + k0_ + seg * 8;            \
            const long gbx = (long)(n0 + row) * 256 + k0_ + seg * 8;           \
            cp16(sbb_ + so,          Ahi + ga);                                \
            cp16(sbb_ + 10240 + so,  Bhi + gbx);                               \
        }                                                                      \
        cp_commit();                                                           \
    } while (0)

    LOAD_CHUNK(0, 0);
    LOAD_CHUNK(1, 1);
    #pragma unroll 1
    for (int ck = 0; ck < 8; ++ck) {
        cp_wait<1>();
        __syncthreads();
        if (ck + 2 < 8) LOAD_CHUNK(ck + 2, (ck + 2) % 3); else cp_commit();
        const uint32_t sbb = sb + (ck % 3) * BUF_MM;
        #pragma unroll
        for (int step = 0; step < 2; ++step) {
            uint32_t av[4][4], bh[4][2];
            #pragma unroll
            for (int mt = 0; mt < 4; ++mt)
                ldsm4(av[mt], sbb + (warpR * 64 + mt * 16) * 80 + step * 32 + aoff);
            #pragma unroll
            for (int ntp = 0; ntp < 2; ++ntp)
                ldsm4(&bh[2 * ntp][0],
                      sbb + 10240 + (warpC * 32 + ntp * 16) * 80 + step * 32 + boff4);
            #pragma unroll
            for (int mt = 0; mt < 4; ++mt)
                #pragma unroll
                for (int nt = 0; nt < 4; ++nt)
                    mma16816(acc[mt][nt], av[mt], bh[nt]);
        }
    }
    #undef LOAD_CHUNK

    #define EPI acc, sm, m0, n0, warpR, warpC, lane, tid, a.Ah, a.Al, a.bias, a.eh0, a.eh1
    if (MODE == M_PROJ3) {
        if (slot == 2)      passF<0>(EPI, a.f0);                  // values fp32
        else if (slot == 1) passN<0, true>(EPI, a.o2h, a.o2l);    // queries
        else                passN<0, true>(EPI, a.ohi, a.olo);    // keys
    } else if (MODE == M_FWD_KT) {
        combinedTF<0>(acc, sm, m0, n0, warpR, warpC, lane, a.Ah, a.Al, a.bias,
                      nullptr, nullptr);
        copyH(sm, m0, n0, tid, a.f0h);                            // g1 = silu'(z1)
        passN<0, true>(EPI, a.ohi, a.olo);                        // h1
    } else if (MODE == M_FWD_Q) {
        passN<2, true>(EPI, a.ohi, a.olo);
    } else if (MODE == M_FWD_OUT) {
        passF<2>(EPI, a.f0);
    } else if (MODE == M_DZ2) {
        combinedTF<1>(acc, sm, m0, n0, warpR, warpC, lane, a.Ah, a.Al, a.bias,
                      a.vals, a.alr);
        copyH(sm, m0, n0, tid, a.f0h);                            // dp fp16
        passN<0, false>(EPI, a.ohi, nullptr);                     // dz2 (hi only)
        biasN(sm, m0, n0, tid, a.gbp);                            // layer-1 bias partials
    } else {                                                      // M_DZ1
        passN<5, false>(EPI, a.ohi, nullptr);                     // dz1 (hi only)
        biasN(sm, m0, n0, tid, a.gbp);                            // layer-0 bias partials
    }
    #undef EPI
}

// ---------------- weight-grad GEMM via ldmatrix.trans on normal layout ------
// C[k1,k2] += sum_n Ah[n][k1]*Bh[n][k2]  (single-pass fp16 hi), 3-buffer pipe.
// grid (2, 2, 64): x=n-tile, y=m-tile, z: [0,32)=h1ᵀ@dz2, [32,64)=keysᵀ@dz1
#define BUF_WG 17408   // Ah(8704) Bh(8704)

struct WGArgs {
    const __half *A1h, *B1h;
    const __half *A2h, *B2h;
    float* part;
};

__global__ __launch_bounds__(256, 2) void wg_k(const WGArgs a)
{
    extern __shared__ char sm[];
    const int tid = threadIdx.x, lane = tid & 31, wid = tid >> 5;
    const int warpR = wid >> 2, warpC = wid & 3;
    const int m0 = blockIdx.y * 128, n0 = blockIdx.x * 128;
    const int gemm = blockIdx.z >> 5;
    const long tokbase = (long)(blockIdx.z & 31) * 1024;
    const uint32_t sb = smem_u32(sm);

    const __half* Ah = gemm ? a.A2h : a.A1h;
    const __half* Bh = gemm ? a.B2h : a.B1h;

    float acc[4][4][4];
    #pragma unroll
    for (int i = 0; i < 4; ++i)
        #pragma unroll
        for (int j = 0; j < 4; ++j)
            #pragma unroll
            for (int e = 0; e < 4; ++e) acc[i][j][e] = 0.f;

    const uint32_t atoff = (uint32_t)((((lane >> 4) & 1) * 8 + (lane & 7)) * 272
                                      + ((lane >> 3) & 1) * 16);
    const uint32_t btoff4 = (uint32_t)(((((lane >> 3) & 1) * 8 + (lane & 7))) * 272
                                       + (lane >> 4) * 16);

    #define WLOAD(ck, buf) do {                                                \
        const long t0 = tokbase + (long)(ck) * 32;                             \
        const uint32_t sbb_ = sb + (buf) * BUF_WG;                             \
        _Pragma("unroll")                                                      \
        for (int rep = 0; rep < 2; ++rep) {                                    \
            const int id = tid + rep * 256;                                    \
            const int row = id >> 4, seg = id & 15;                            \
            const uint32_t so = row * 272 + seg * 16;                          \
            const long gA = (t0 + row) * 256 + m0 + seg * 8;                   \
            const long gB = (t0 + row) * 256 + n0 + seg * 8;                   \
            cp16(sbb_ + so,         Ah + gA);                                  \
            cp16(sbb_ + 8704 + so,  Bh + gB);                                  \
        }                                                                      \
        cp_commit();                                                           \
    } while (0)

    WLOAD(0, 0);
    WLOAD(1, 1);
    #pragma unroll 1
    for (int ck = 0; ck < 32; ++ck) {
        cp_wait<1>();
        __syncthreads();
        if (ck + 2 < 32) WLOAD(ck + 2, (ck + 2) % 3); else cp_commit();
        const uint32_t sbb = sb + (ck % 3) * BUF_WG;
        #pragma unroll
        for (int step = 0; step < 2; ++step) {
            const uint32_t ks = step * 16 * 272;
            uint32_t av[4][4], bh[4][2];
            #pragma unroll
            for (int mt = 0; mt < 4; ++mt)
                ldsm4t(av[mt], sbb + ks + atoff + (warpR * 64 + mt * 16) * 2);
            #pragma unroll
            for (int ntp = 0; ntp < 2; ++ntp) {
                const uint32_t nb = (warpC * 32 + ntp * 16) * 2;
                ldsm4t(&bh[2 * ntp][0], sbb + 8704 + ks + btoff4 + nb);
            }
            #pragma unroll
            for (int mt = 0; mt < 4; ++mt)
                #pragma unroll
                for (int nt = 0; nt < 4; ++nt)
                    mma16816(acc[mt][nt], av[mt], bh[nt]);
        }
    }
    #undef WLOAD

    passF<0>(acc, sm, m0, n0, warpR, warpC, lane, tid, nullptr, nullptr,
             nullptr, nullptr, nullptr, a.part + (size_t)blockIdx.z * DD);
}

// ---------------- fused prep: x split + adaptive lr + weight prep -----------
// blocks [0, NTOK/8): xsplit+alr.  blocks [NTOK/8, NTOK/8 + 6*DD/256): wprep.
__global__ void prep_k(const float* __restrict__ x, const float* __restrict__ Wlr,
                       const float* __restrict__ blr,
                       const float* __restrict__ Wk, const float* __restrict__ Wq,
                       const float* __restrict__ Wv, const float* __restrict__ Ws,
                       __half* __restrict__ xh, float* __restrict__ alr,
                       __half* __restrict__ wh)
{
    const int b = blockIdx.x;
    if (b < NTOK / 8) {
        const int warp = threadIdx.x >> 5, lane = threadIdx.x & 31;
        const long tok = (long)b * 8 + warp;
        const float* xr = x + tok * 256 + lane * 8;
        float4 va = *(const float4*)xr;
        float4 vb = *(const float4*)(xr + 4);
        float v[8] = {va.x, va.y, va.z, va.w, vb.x, vb.y, vb.z, vb.w};
        const float* wr = Wlr + lane * 8;
        float dot = 0.f;
        ushort hs[8];
        #pragma unroll
        for (int j = 0; j < 8; ++j) {
            dot += v[j] * wr[j];
            hs[j] = __half_as_ushort(__float2half_rn(v[j]));
        }
        *(uint4*)(xh + tok * 256 + lane * 8) = *(uint4*)hs;
        #pragma unroll
        for (int o = 16; o > 0; o >>= 1) dot += __shfl_xor_sync(0xffffffffu, dot, o);
        if (lane == 0) alr[tok] = 0.1f * sigm(dot + blr[0]);
    } else {
        // slots: 0=Wk^T 1=Wq^T 2=Wv^T 3=W0^T 4=W1^T 5=W1
        const int idx = (b - NTOK / 8) * 256 + threadIdx.x;
        const int slot = idx >> 16;
        const int r = (idx >> 8) & 255;
        const int c = idx & 255;
        float v;
        if      (slot == 0) v = Wk[c * 256 + r];
        else if (slot == 1) v = Wq[c * 256 + r];
        else if (slot == 2) v = Wv[c * 256 + r];
        else if (slot == 3) v = Ws[c * 256 + r];
        else if (slot == 4) v = Ws[DD + c * 256 + r];
        else                v = Ws[DD + r * 256 + c];
        wh[idx] = __float2half_rn(v);
    }
}

// ---- fused reduce + AdamW: -grads to out, fp16 transposed updated weights --
// part slices 0..31 = h1^T@dz2 (gW1/layer1); 32..63 = keys^T@dz1 (gW0/layer0)
__global__ void adamw_f(const float* __restrict__ Ws, const float* __restrict__ bs,
                        const float* __restrict__ part, const float* __restrict__ gbp,
                        __half* __restrict__ nwth, float* __restrict__ nb,
                        float* __restrict__ out)
{
    const int idx = blockIdx.x * 256 + threadIdx.x;
    const float decay = 1.0f - LRc * WDc;
    if (idx < 2 * DD) {
        const int layer = idx >> 16;
        const int j = idx & 65535;
        const int zbase = (layer == 0) ? 32 : 0;
        float g = 0.0f;
        #pragma unroll 4
        for (int z = 0; z < 32; ++z) g += part[(size_t)(zbase + z) * DD + j];
        out[ND + idx] = -g;
        const float nw = Ws[idx] * decay - LRc * g / (fabsf(g) + EPSc);
        const int k = (idx >> 8) & 255;
        const int n = idx & 255;
        nwth[(long)layer * DD + n * 256 + k] = __float2half_rn(nw);
    } else if (idx < 2 * DD + 2 * D) {
        const int b = idx - 2 * DD;
        const int layer = b >> 8;
        const int j = b & 255;
        const float* p = gbp + (size_t)layer * 65536;
        float g = 0.f;
        for (int mt = 0; mt < 256; ++mt) g += p[mt * 256 + j];
        out[ND + 2 * DD + b] = -g;
        nb[b] = bs[b] * decay - LRc * g / (fabsf(g) + EPSc);
    }
}

// ---------------------------------------------------------------------------
extern "C" void kernel_launch(void* const* d_in, const int* in_sizes, int n_in,
                              void* d_out, int out_size)
{
    const float* x   = (const float*)d_in[0];
    const float* Wk  = (const float*)d_in[1];
    const float* Wq  = (const float*)d_in[2];
    const float* Wv  = (const float*)d_in[3];
    const float* Wlr = (const float*)d_in[4];
    const float* blr = (const float*)d_in[5];
    const float* Ws  = (const float*)d_in[6];
    const float* bs  = (const float*)d_in[7];
    float* out = (float*)d_out;

    #define SYM(T, v, s) T* v; cudaGetSymbolAddress((void**)&v, s)
    SYM(__half, xbh, g_xbh);
    SYM(__half, keysh, g_keysh); SYM(__half, keysl, g_keysl);
    SYM(__half, qh, g_qh);     SYM(__half, ql, g_ql);
    SYM(__half, h1h, g_h1h);   SYM(__half, h1l, g_h1l);
    SYM(__half, dz2h, g_dz2h);
    SYM(__half, dz1h, g_dz1h);
    SYM(__half, h1qh, g_h1qh); SYM(__half, h1ql, g_h1ql);
    SYM(__half, g1, g_g1);     SYM(__half, dp, g_dp);
    SYM(__half, wbh, g_wbh);
    SYM(__half, nwth, g_nwth);
    SYM(float, values, g_values);
    SYM(float, part, g_part); SYM(float, gbp, g_gbp);
    SYM(float, nb, g_nb); SYM(float, alr, g_alr);
    #undef SYM

    #define SETSM(M) cudaFuncSetAttribute(mm_k<M>, \
        cudaFuncAttributeMaxDynamicSharedMemorySize, SMEM_BYTES)
    SETSM(M_PROJ3); SETSM(M_FWD_KT); SETSM(M_FWD_Q);
    SETSM(M_FWD_OUT); SETSM(M_DZ2); SETSM(M_DZ1);
    #undef SETSM
    cudaFuncSetAttribute(wg_k, cudaFuncAttributeMaxDynamicSharedMemorySize, SMEM_BYTES);

    // fused prep: x->fp16 + alr + weight transposes
    prep_k<<<NTOK / 8 + 6 * DD / 256, 256>>>(x, Wlr, blr, Wk, Wq, Wv, Ws,
                                             xbh, alr, wbh);

    MMArgs a = {};
    // fused projections: keys, queries, values
    a.Ah = xbh; a.Bh = wbh;
    a.ohi = keysh; a.olo = keysl; a.o2h = qh; a.o2l = ql; a.f0 = values;
    mm_k<M_PROJ3><<<dim3(6, 256), 256, SMEM_BYTES>>>(a);

    // forward on keys: g1=silu'(z1) fp16 + h1 (fp16 pair)
    a = {};
    a.Ah = keysh; a.Al = keysl; a.Bh = wbh + 3 * DD;
    a.bias = bs; a.f0h = g1; a.ohi = h1h; a.olo = h1l;
    mm_k<M_FWD_KT><<<dim3(2, 256), 256, SMEM_BYTES>>>(a);

    // dz2 + dp(fp16) + layer-1 bias partials (z2 recomputed in epilogue)
    a = {};
    a.Ah = h1h; a.Al = h1l; a.Bh = wbh + 4 * DD;
    a.bias = bs + D; a.vals = values; a.alr = alr; a.f0h = dp;
    a.ohi = dz2h; a.gbp = gbp + 65536;
    mm_k<M_DZ2><<<dim3(2, 256), 256, SMEM_BYTES>>>(a);

    // dz1 = (dp + dz2 @ W1^T) * silu'(z1)  + layer-0 bias partials
    a = {};
    a.Ah = dz2h; a.Bh = wbh + 5 * DD;
    a.eh0 = dp; a.eh1 = g1; a.ohi = dz1h; a.gbp = gbp;
    mm_k<M_DZ1><<<dim3(2, 256), 256, SMEM_BYTES>>>(a);

    // weight grads, single-pass hi (split-K 32 each)
    WGArgs w = {};
    w.A1h = h1h;   w.B1h = dz2h;
    w.A2h = keysh; w.B2h = dz1h;
    w.part = part;
    wg_k<<<dim3(2, 2, 64), 256, SMEM_BYTES>>>(w);

    // fused: split-K reduce + bias reduce + AdamW + emit -grads
    adamw_f<<<(2 * DD + 2 * D + 255) / 256, 256>>>(Ws, bs, part, gbp,
                                                   nwth, nb, out);

    // retrieved = forward(queries) with updated weights
    a = {};
    a.Ah = qh; a.Al = ql; a.Bh = nwth;
    a.bias = nb; a.ohi = h1qh; a.olo = h1ql;
    mm_k<M_FWD_Q><<<dim3(2, 256), 256, SMEM_BYTES>>>(a);

    a = {};
    a.Ah = h1qh; a.Al = h1ql; a.Bh = nwth + DD;
    a.bias = nb + D; a.f0 = out;
    mm_k<M_FWD_OUT><<<dim3(2, 256), 256, SMEM_BYTES>>>(a);
}